// round 11
// baseline (speedup 1.0000x reference)
#include <cuda_runtime.h>
#include <cuda_bf16.h>

// ann2_snn1: sigmoid -> feature-uniform dual-exp IIR -> W proj (500->10) -> LIF spikes
// inputs [64,500,1024] f32; a1,a2 [500]; W [10,500]; b [10]; out [64,10,1024] f32
//
// IIR coeffs are feature-uniform => IIR commutes with the projection:
//   W @ IIR(sig(x)) == IIR(W @ sig(x))
// Kernel 1 (this round's target): time-parallel projection. R10 analysis puts it
//   at ~50us, ~2x over its fma-pipe floor. Fix: 2 t per thread + fma.rn.f32x2
//   (SASS FFMA2, unreachable from C++) halves fma-pipe + issue work.
// Kernel 2: byte-identical to R10 (measured 25.95us).

#define B_ 64
#define F_ 500
#define T_ 1024
#define O_ 10
#define CH (B_ * O_)   // 640 channels

// scratch: u[t][b*10+o]  (2.62 MB, L2-resident)
__device__ float g_u[(size_t)T_ * CH];

// ---- packed f32x2 helpers (sm_103a FFMA2 path) ------------------------------
__device__ __forceinline__ unsigned long long pack_f32x2(float lo, float hi) {
    unsigned long long r;
    asm("mov.b64 %0, {%1, %2};" : "=l"(r) : "f"(lo), "f"(hi));
    return r;
}
__device__ __forceinline__ void unpack_f32x2(unsigned long long v, float& lo, float& hi) {
    asm("mov.b64 {%0, %1}, %2;" : "=f"(lo), "=f"(hi) : "l"(v));
}
__device__ __forceinline__ unsigned long long fma_f32x2(unsigned long long a,
                                                        unsigned long long b,
                                                        unsigned long long c) {
    unsigned long long d;
    asm("fma.rn.f32x2 %0, %1, %2, %3;" : "=l"(d) : "l"(a), "l"(b), "l"(c));
    return d;
}

// ---------------------------------------------------------------------------
// Kernel 1: u[t, b, o] = sum_f W[o,f] * sigmoid(inputs[b, f, t])
// block = 64 threads, each handling 2 adjacent t (float2 load -> FFMA2 pair).
// grid = (T/128, B) = (8, 64) = 512 blocks.
// W staged in smem as duplicated {w,w} 64-bit pairs: 500 rows x 5 ulonglong2.
// ---------------------------------------------------------------------------
__global__ void __launch_bounds__(64) proj_kernel(const float* __restrict__ in,
                                                  const float* __restrict__ W) {
    __shared__ ulonglong2 Wsh[F_ * 5];   // [f][j] holds o=2j,2j+1 as {w,w} pairs; 40KB

    const int tid = threadIdx.x;
    const int b   = blockIdx.y;
    const int t   = blockIdx.x * 128 + tid * 2;   // this thread: t, t+1

    // stage W duplicated: element i -> (f = i/10, o = i%10)
    {
        unsigned long long* Wflat = (unsigned long long*)Wsh;
        for (int i = tid; i < F_ * O_; i += 64) {
            int f = i / O_;
            int o = i - f * O_;
            float w = W[o * F_ + f];
            Wflat[f * 10 + o] = pack_f32x2(w, w);
        }
    }
    __syncthreads();

    const float2* row = (const float2*)(in + (size_t)b * (F_ * T_) + t);
    // row + f*(T_/2) advances one feature (T_ floats = T_/2 float2)

    unsigned long long acc[O_];
#pragma unroll
    for (int o = 0; o < O_; o++) acc[o] = 0ull;

#pragma unroll 8
    for (int f = 0; f < F_; f++) {
        float2 x = __ldg(row + (size_t)f * (T_ / 2));
        // sigmoid per half — identical ops/rounding to the verified R7/R10 path
        float e0 = __expf(-x.x);
        float s0 = __fdividef(1.0f, 1.0f + e0);
        float e1 = __expf(-x.y);
        float s1 = __fdividef(1.0f, 1.0f + e1);
        unsigned long long s2 = pack_f32x2(s0, s1);

        const ulonglong2* wrow = &Wsh[f * 5];
#pragma unroll
        for (int j = 0; j < 5; j++) {
            ulonglong2 w2 = wrow[j];                    // LDS.128: o=2j, 2j+1
            acc[2 * j + 0] = fma_f32x2(w2.x, s2, acc[2 * j + 0]);
            acc[2 * j + 1] = fma_f32x2(w2.y, s2, acc[2 * j + 1]);
        }
    }

    float* up0 = g_u + (size_t)t * CH + b * O_;        // row for t
    float* up1 = up0 + CH;                             // row for t+1
#pragma unroll
    for (int o = 0; o < O_; o++) {
        float lo, hi;
        unpack_f32x2(acc[o], lo, hi);
        up0[o] = lo;
        up1[o] = hi;
    }
}

// ---------------------------------------------------------------------------
// Kernel 2: smem-staged serial IIR + LIF.   [byte-identical to R10, 25.95us]
// grid = 20 blocks x 128 threads. Block owns 32 channels.
// Phase 1: all 4 warps stage u[0..1023][ch0..ch0+31] (128 KB) into smem.
// Phase 2: warp 0 runs the 1024-step serial chain from 29-cyc LDS.
// ---------------------------------------------------------------------------
#define TILE_ 16
#define SMEM_BYTES (T_ * 32 * sizeof(float))   // 131072

__global__ void __launch_bounds__(128) iir_lif_kernel(const float* __restrict__ a1p,
                                                      const float* __restrict__ a2p,
                                                      const float* __restrict__ bias,
                                                      float* __restrict__ out) {
    extern __shared__ float sm[];   // sm[t*32 + lane]

    const int tid = threadIdx.x;
    const int ch0 = blockIdx.x * 32;

    // Phase 1: coalesced stage-in. 8 float4 per t-row; i covers T_*8 = 8192 vecs.
    {
        float4* dst = (float4*)sm;
        for (int i = tid; i < T_ * 8; i += 128) {
            int t = i >> 3;
            int j = i & 7;
            dst[i] = *(const float4*)(g_u + (size_t)t * CH + ch0 + j * 4);
        }
    }
    __syncthreads();
    if (tid >= 32) return;          // warps 1-3 done (no further barriers)

    const int ch = ch0 + tid;
    const int b  = ch / O_;
    const int o  = ch - b * O_;

    const float a1 = __ldg(a1p);    // feature-uniform
    const float a2 = __ldg(a2p);
    const float bo = __ldg(bias + o);
    const float dm = 0.7788007830714049f;   // exp(-1/4)

    float y1 = 0.f, y2 = 0.f, v = 0.f;
    bool fired = false;

    float* orow = out + (size_t)b * (O_ * T_) + (size_t)o * T_;
    const float* mysm = sm + tid;   // stride 32 floats per t, conflict-free

    for (int t0 = 0; t0 < T_; t0 += TILE_) {
        // pull 16 steps from smem (29-cyc LDS, batched; independent of chain)
        float xt[TILE_];
#pragma unroll
        for (int i = 0; i < TILE_; i++) xt[i] = mysm[(t0 + i) * 32];

        float sbuf[TILE_];
#pragma unroll
        for (int i = 0; i < TILE_; i++) {
            // IIR: exact rounding order of the reference (mul, mul, add, add)
            float y = __fadd_rn(__fadd_rn(__fmul_rn(a1, y1), __fmul_rn(a2, y2)), xt[i]);
            y2 = y1;
            y1 = y;
            float psc = __fadd_rn(y, bo);
            // leak path computed in parallel with the fired-predicate
            float vleak = __fadd_rn(__fmul_rn(dm, v), psc);
            v = fired ? psc : vleak;
            fired = (v > 1.0f);
            sbuf[i] = fired ? 1.0f : 0.0f;
        }

        // vectorized stores, off the critical path
        float4* o4 = (float4*)(orow + t0);
#pragma unroll
        for (int i = 0; i < TILE_ / 4; i++)
            o4[i] = make_float4(sbuf[4*i], sbuf[4*i+1], sbuf[4*i+2], sbuf[4*i+3]);
    }
}

// ---------------------------------------------------------------------------
extern "C" void kernel_launch(void* const* d_in, const int* in_sizes, int n_in,
                              void* d_out, int out_size) {
    (void)in_sizes; (void)n_in; (void)out_size;
    const float* inputs = (const float*)d_in[0];   // [64, 500, 1024]
    const float* a1     = (const float*)d_in[1];   // [500]
    const float* a2     = (const float*)d_in[2];   // [500]
    const float* W      = (const float*)d_in[3];   // [10, 500]
    const float* bias   = (const float*)d_in[4];   // [10]
    float*       out    = (float*)d_out;           // [64, 10, 1024]

    // 128 KB dynamic smem for the stage-in buffer (host-side config; no alloc)
    cudaFuncSetAttribute(iir_lif_kernel,
                         cudaFuncAttributeMaxDynamicSharedMemorySize, SMEM_BYTES);

    dim3 g1(T_ / 128, B_);
    proj_kernel<<<g1, 64>>>(inputs, W);

    iir_lif_kernel<<<CH / 32, 128, SMEM_BYTES>>>(a1, a2, bias, out);
}

// round 12
// speedup vs baseline: 1.2423x; 1.2423x over previous
#include <cuda_runtime.h>
#include <cuda_bf16.h>

// ann2_snn1: sigmoid -> feature-uniform dual-exp IIR -> W proj (500->10) -> LIF spikes
// inputs [64,500,1024] f32; a1,a2 [500]; W [10,500]; b [10]; out [64,10,1024] f32
//
// IIR coeffs are feature-uniform => IIR commutes with the projection:
//   W @ IIR(sig(x)) == IIR(W @ sig(x))
//
// R11 post-mortem: FFMA2 + 64-thr blocks REGRESSED proj (50->59us) => proj is
// load-latency bound, not fma-bound. R12: revert to the R10 proj (128-thr,
// scalar FFMA) with ONE change: unroll 8 -> 20, raising in-flight bytes/SM
// from ~14KB to ~35KB (> ~21KB BW*latency product) to saturate HBM.
// Kernel 2: byte-identical to R10/R11 (measured 25.3-25.9us).

#define B_ 64
#define F_ 500
#define T_ 1024
#define O_ 10
#define CH (B_ * O_)   // 640 channels

// scratch: u[t][b*10+o]  (2.62 MB, L2-resident)
__device__ float g_u[(size_t)T_ * CH];

// ---------------------------------------------------------------------------
// Kernel 1: u[t, b, o] = sum_f W[o,f] * sigmoid(inputs[b, f, t])
// grid = (T/128, B), block = 128 (one t per thread)
// ---------------------------------------------------------------------------
__global__ void __launch_bounds__(128) proj_kernel(const float* __restrict__ in,
                                                   const float* __restrict__ W) {
    __shared__ float Wsh[F_ * 12];   // padded to 12 floats/row -> 3x float4

    const int tid = threadIdx.x;
    const int b   = blockIdx.y;
    const int t   = blockIdx.x * 128 + tid;

    for (int i = tid; i < F_ * 12; i += 128) {
        int f = i / 12;
        int o = i - f * 12;
        Wsh[i] = (o < O_) ? W[o * F_ + f] : 0.0f;
    }
    __syncthreads();

    const float* row = in + (size_t)b * (F_ * T_) + t;
    const float4* W4 = (const float4*)Wsh;

    float acc0 = 0.f, acc1 = 0.f, acc2 = 0.f, acc3 = 0.f, acc4 = 0.f;
    float acc5 = 0.f, acc6 = 0.f, acc7 = 0.f, acc8 = 0.f, acc9 = 0.f;

    // unroll 20 (500 = 20*25, no remainder): 20 independent LDGs in flight per
    // warp -> ~35KB/SM outstanding at 13.8 warps/SM, saturating DRAM.
#pragma unroll 20
    for (int f = 0; f < F_; f++) {
        float x = __ldg(row + (size_t)f * T_);
        float e = __expf(-x);
        float s = __fdividef(1.0f, 1.0f + e);

        float4 w0 = W4[f * 3 + 0];
        float4 w1 = W4[f * 3 + 1];
        float4 w2 = W4[f * 3 + 2];

        acc0 += w0.x * s;  acc1 += w0.y * s;  acc2 += w0.z * s;  acc3 += w0.w * s;
        acc4 += w1.x * s;  acc5 += w1.y * s;  acc6 += w1.z * s;  acc7 += w1.w * s;
        acc8 += w2.x * s;  acc9 += w2.y * s;
    }

    float* up = g_u + (size_t)t * CH + b * O_;
    up[0] = acc0;  up[1] = acc1;  up[2] = acc2;  up[3] = acc3;  up[4] = acc4;
    up[5] = acc5;  up[6] = acc6;  up[7] = acc7;  up[8] = acc8;  up[9] = acc9;
}

// ---------------------------------------------------------------------------
// Kernel 2: smem-staged serial IIR + LIF.   [byte-identical to R10/R11]
// grid = 20 blocks x 128 threads. Block owns 32 channels.
// Phase 1: all 4 warps stage u[0..1023][ch0..ch0+31] (128 KB) into smem.
// Phase 2: warp 0 runs the 1024-step serial chain from 29-cyc LDS.
// ---------------------------------------------------------------------------
#define TILE_ 16
#define SMEM_BYTES (T_ * 32 * sizeof(float))   // 131072

__global__ void __launch_bounds__(128) iir_lif_kernel(const float* __restrict__ a1p,
                                                      const float* __restrict__ a2p,
                                                      const float* __restrict__ bias,
                                                      float* __restrict__ out) {
    extern __shared__ float sm[];   // sm[t*32 + lane]

    const int tid = threadIdx.x;
    const int ch0 = blockIdx.x * 32;

    // Phase 1: coalesced stage-in. 8 float4 per t-row; i covers T_*8 = 8192 vecs.
    {
        float4* dst = (float4*)sm;
        for (int i = tid; i < T_ * 8; i += 128) {
            int t = i >> 3;
            int j = i & 7;
            dst[i] = *(const float4*)(g_u + (size_t)t * CH + ch0 + j * 4);
        }
    }
    __syncthreads();
    if (tid >= 32) return;          // warps 1-3 done (no further barriers)

    const int ch = ch0 + tid;
    const int b  = ch / O_;
    const int o  = ch - b * O_;

    const float a1 = __ldg(a1p);    // feature-uniform
    const float a2 = __ldg(a2p);
    const float bo = __ldg(bias + o);
    const float dm = 0.7788007830714049f;   // exp(-1/4)

    float y1 = 0.f, y2 = 0.f, v = 0.f;
    bool fired = false;

    float* orow = out + (size_t)b * (O_ * T_) + (size_t)o * T_;
    const float* mysm = sm + tid;   // stride 32 floats per t, conflict-free

    for (int t0 = 0; t0 < T_; t0 += TILE_) {
        // pull 16 steps from smem (29-cyc LDS, batched; independent of chain)
        float xt[TILE_];
#pragma unroll
        for (int i = 0; i < TILE_; i++) xt[i] = mysm[(t0 + i) * 32];

        float sbuf[TILE_];
#pragma unroll
        for (int i = 0; i < TILE_; i++) {
            // IIR: exact rounding order of the reference (mul, mul, add, add)
            float y = __fadd_rn(__fadd_rn(__fmul_rn(a1, y1), __fmul_rn(a2, y2)), xt[i]);
            y2 = y1;
            y1 = y;
            float psc = __fadd_rn(y, bo);
            // leak path computed in parallel with the fired-predicate
            float vleak = __fadd_rn(__fmul_rn(dm, v), psc);
            v = fired ? psc : vleak;
            fired = (v > 1.0f);
            sbuf[i] = fired ? 1.0f : 0.0f;
        }

        // vectorized stores, off the critical path
        float4* o4 = (float4*)(orow + t0);
#pragma unroll
        for (int i = 0; i < TILE_ / 4; i++)
            o4[i] = make_float4(sbuf[4*i], sbuf[4*i+1], sbuf[4*i+2], sbuf[4*i+3]);
    }
}

// ---------------------------------------------------------------------------
extern "C" void kernel_launch(void* const* d_in, const int* in_sizes, int n_in,
                              void* d_out, int out_size) {
    (void)in_sizes; (void)n_in; (void)out_size;
    const float* inputs = (const float*)d_in[0];   // [64, 500, 1024]
    const float* a1     = (const float*)d_in[1];   // [500]
    const float* a2     = (const float*)d_in[2];   // [500]
    const float* W      = (const float*)d_in[3];   // [10, 500]
    const float* bias   = (const float*)d_in[4];   // [10]
    float*       out    = (float*)d_out;           // [64, 10, 1024]

    // 128 KB dynamic smem for the stage-in buffer (host-side config; no alloc)
    cudaFuncSetAttribute(iir_lif_kernel,
                         cudaFuncAttributeMaxDynamicSharedMemorySize, SMEM_BYTES);

    dim3 g1(T_ / 128, B_);
    proj_kernel<<<g1, 128>>>(inputs, W);

    iir_lif_kernel<<<CH / 32, 128, SMEM_BYTES>>>(a1, a2, bias, out);
}